// round 13
// baseline (speedup 1.0000x reference)
#include <cuda_runtime.h>
#include <cuda_bf16.h>
#include <cstdint>

// Problem constants
#define BB 8
#define NN 128
#define CC 3
#define FF 64
#define KK 64

// Scratch for projections: p[row][kk], row = (b*N+n)*C+c (3072 rows), kk in [0,128):
// kk<64 -> p_i + b_vs (bias folded in), kk>=64 -> p_j.
__device__ float g_p[BB * NN * CC * 128];

// ---- packed f32x2 helpers (sm_100+) --------------------------------------
__device__ __forceinline__ unsigned long long add2(unsigned long long a, unsigned long long b) {
    unsigned long long r; asm("add.rn.f32x2 %0, %1, %2;" : "=l"(r) : "l"(a), "l"(b)); return r;
}
__device__ __forceinline__ unsigned long long mul2(unsigned long long a, unsigned long long b) {
    unsigned long long r; asm("mul.rn.f32x2 %0, %1, %2;" : "=l"(r) : "l"(a), "l"(b)); return r;
}
__device__ __forceinline__ unsigned long long fma2(unsigned long long a, unsigned long long b,
                                                   unsigned long long c) {
    unsigned long long r; asm("fma.rn.f32x2 %0, %1, %2, %3;" : "=l"(r) : "l"(a), "l"(b), "l"(c));
    return r;
}
__device__ __forceinline__ void unpk2(unsigned long long p, float& lo, float& hi) {
    asm("mov.b64 {%0, %1}, %2;" : "=f"(lo), "=f"(hi) : "l"(p));
}

__device__ __forceinline__ uint32_t smem_u32(const void* p) {
    uint32_t a;
    asm("{ .reg .u64 t; cvta.to.shared.u64 t, %1; cvt.u32.u64 %0, t; }" : "=r"(a) : "l"(p));
    return a;
}

// ---------------------------------------------------------------------------
// Kernel 1: p[row][kk] = sum_f vf[row][f] * ws[f][kk]  (+ b_vs[kk] if kk<64)
// 96 blocks x 256 threads; 32 rows per block. Ends with PDL launch_dependents.
// ---------------------------------------------------------------------------
__global__ __launch_bounds__(256)
void proj_kernel(const float* __restrict__ vf, const float* __restrict__ w,
                 const float* __restrict__ bvs)
{
    __shared__ float ws[FF * 128];   // 32 KB: rearranged weights [f][kk]
    __shared__ float vfs[32 * FF];   // 8 KB: this block's 32 vf rows

    const int tid = threadIdx.x;

    #pragma unroll
    for (int idx = tid; idx < FF * 128; idx += 256) {
        int f  = idx >> 7;
        int kk = idx & 127;
        ws[idx] = (kk < 64) ? w[f * 64 + kk] : w[(64 + f) * 64 + (kk - 64)];
    }

    const int r0 = blockIdx.x * 32;
    const float4* vf4 = reinterpret_cast<const float4*>(vf + (size_t)r0 * FF);
    float4* vfs4 = reinterpret_cast<float4*>(vfs);
    #pragma unroll
    for (int idx = tid; idx < 32 * (FF / 4); idx += 256)
        vfs4[idx] = vf4[idx];

    __syncthreads();

    const int kg = tid & 31;   // float4 group over kk
    const int rv = tid >> 5;   // 0..7

    float4 acc0 = make_float4(0.f, 0.f, 0.f, 0.f);
    float4 acc1 = acc0, acc2 = acc0, acc3 = acc0;

    const float4* ws4 = reinterpret_cast<const float4*>(ws); // [64][32]

    #pragma unroll 8
    for (int f = 0; f < FF; ++f) {
        float4 w4 = ws4[f * 32 + kg];
        float v0 = vfs[(rv     ) * FF + f];
        float v1 = vfs[(rv +  8) * FF + f];
        float v2 = vfs[(rv + 16) * FF + f];
        float v3 = vfs[(rv + 24) * FF + f];
        acc0.x += v0 * w4.x; acc0.y += v0 * w4.y; acc0.z += v0 * w4.z; acc0.w += v0 * w4.w;
        acc1.x += v1 * w4.x; acc1.y += v1 * w4.y; acc1.z += v1 * w4.z; acc1.w += v1 * w4.w;
        acc2.x += v2 * w4.x; acc2.y += v2 * w4.y; acc2.z += v2 * w4.z; acc2.w += v2 * w4.w;
        acc3.x += v3 * w4.x; acc3.y += v3 * w4.y; acc3.z += v3 * w4.z; acc3.w += v3 * w4.w;
    }

    if (kg < 16) {   // bias folded into the p_i half
        const float4 bv = reinterpret_cast<const float4*>(bvs)[kg];
        acc0.x += bv.x; acc0.y += bv.y; acc0.z += bv.z; acc0.w += bv.w;
        acc1.x += bv.x; acc1.y += bv.y; acc1.z += bv.z; acc1.w += bv.w;
        acc2.x += bv.x; acc2.y += bv.y; acc2.z += bv.z; acc2.w += bv.w;
        acc3.x += bv.x; acc3.y += bv.y; acc3.z += bv.z; acc3.w += bv.w;
    }

    float4* p4 = reinterpret_cast<float4*>(g_p); // [3072][32]
    p4[(size_t)(r0 + rv     ) * 32 + kg] = acc0;
    p4[(size_t)(r0 + rv +  8) * 32 + kg] = acc1;
    p4[(size_t)(r0 + rv + 16) * 32 + kg] = acc2;
    p4[(size_t)(r0 + rv + 24) * 32 + kg] = acc3;

    asm volatile("griddepcontrol.launch_dependents;" ::: "memory");
}

// ---------------------------------------------------------------------------
// Kernel 2: out[b,i,j,k] = relu( sum_c d[b,i,j,c] * (p_i'[b,i,c,k] + p_j[b,j,c,k]) )
// grid (jg=8, it=16, b=8) = 1024 blocks x 256 threads; block = 8 i x 16 j.
// Inner loop: LDS + packed f32x2 + STS.128 into a 32KB smem out-tile
// (NO STG in the loop). Epilogue: 8x cp.async.bulk smem->gmem (4KB each,
// contiguous), driven by the async engine instead of the LSU/L1TEX path.
// ---------------------------------------------------------------------------
__global__ __launch_bounds__(256, 5)
void fuse_kernel(const float* __restrict__ dist,
                 float* __restrict__ out)
{
    __shared__ float4 pi_s[8 * 3 * 16];               // [(ii*3+c)][kq]   6 KB
    __shared__ unsigned long long dist_p[8 * 16 * 4]; // [ii][jl][c,pad]  4 KB
    __shared__ float4 out_s[8 * 16 * 16];             // [ii][jl][kq]    32 KB

    const int tid = threadIdx.x;
    const int kq  = tid & 15;   // k quad: k = kq*4
    const int jl  = tid >> 4;   // 0..15
    const int j0  = blockIdx.x * 16;
    const int i0  = blockIdx.y * 8;
    const int b   = blockIdx.z;

    // ---- Stage dist first (independent of proj's g_p) ----
    if (tid < 192) {
        const int li  = 2 * tid;             // linear float index in tile
        const int ii  = li / 48;
        const int rem = li % 48;
        const float2 dv = *reinterpret_cast<const float2*>(
            dist + (size_t)(b * NN + i0 + ii) * NN * CC + j0 * CC + rem);
        unsigned long long p0, p1;
        asm("mov.b64 %0, {%1, %1};" : "=l"(p0) : "f"(dv.x));
        asm("mov.b64 %0, {%1, %1};" : "=l"(p1) : "f"(dv.y));
        const int jl0 = rem / 3,       c0 = rem - 3 * jl0;
        const int jl1 = (rem + 1) / 3, c1 = (rem + 1) - 3 * jl1;
        dist_p[(ii * 16 + jl0) * 4 + c0] = p0;
        dist_p[(ii * 16 + jl1) * 4 + c1] = p1;
    }

    // ---- PDL wait: proj's g_p stores visible after this ----
    asm volatile("griddepcontrol.wait;" ::: "memory");

    const float4* p4 = reinterpret_cast<const float4*>(g_p);        // [3072][32]
    const ulonglong2* p4u = reinterpret_cast<const ulonglong2*>(g_p);
    const int rowbase = (b * NN + i0) * CC;                         // 24 rows

    // pj in registers (issued before pi staging: shares the MLP window)
    const int j = j0 + jl;
    const int rowj = (b * NN + j) * CC;
    const ulonglong2 pj0 = p4u[(size_t)(rowj    ) * 32 + 16 + kq];
    const ulonglong2 pj1 = p4u[(size_t)(rowj + 1) * 32 + 16 + kq];
    const ulonglong2 pj2 = p4u[(size_t)(rowj + 2) * 32 + 16 + kq];

    // Stage p_i: 384 float4 (24 rows x 16 float4)
    {
        const int r = tid >> 4, kk = tid & 15;
        pi_s[tid] = p4[(size_t)(rowbase + r) * 32 + kk];
        if (tid < 128) {
            const int idx2 = tid + 256;
            const int r2 = idx2 >> 4, kk2 = idx2 & 15;
            pi_s[idx2] = p4[(size_t)(rowbase + r2) * 32 + kk2];
        }
    }

    __syncthreads();

    const ulonglong2* pi_u = reinterpret_cast<const ulonglong2*>(pi_s);

    #pragma unroll
    for (int ii = 0; ii < 8; ++ii) {
        const ulonglong2 pi0 = pi_u[(ii * 3 + 0) * 16 + kq];
        const ulonglong2 pi1 = pi_u[(ii * 3 + 1) * 16 + kq];
        const ulonglong2 pi2 = pi_u[(ii * 3 + 2) * 16 + kq];
        const ulonglong2 d01 =
            *reinterpret_cast<const ulonglong2*>(&dist_p[(ii * 16 + jl) * 4]);
        const unsigned long long d2 = dist_p[(ii * 16 + jl) * 4 + 2];

        unsigned long long alo = mul2(d01.x, add2(pi0.x, pj0.x));
        alo = fma2(d01.y, add2(pi1.x, pj1.x), alo);
        alo = fma2(d2,    add2(pi2.x, pj2.x), alo);

        unsigned long long ahi = mul2(d01.x, add2(pi0.y, pj0.y));
        ahi = fma2(d01.y, add2(pi1.y, pj1.y), ahi);
        ahi = fma2(d2,    add2(pi2.y, pj2.y), ahi);

        float4 a;
        unpk2(alo, a.x, a.y);
        unpk2(ahi, a.z, a.w);
        a.x = fmaxf(a.x, 0.f);
        a.y = fmaxf(a.y, 0.f);
        a.z = fmaxf(a.z, 0.f);
        a.w = fmaxf(a.w, 0.f);

        out_s[(ii * 16 + jl) * 16 + kq] = a;   // STS.128, conflict-free
    }

    __syncthreads();

    // ---- Epilogue: async bulk-copy the 8 contiguous 4KB slices to gmem ----
    if (tid == 0) {
        asm volatile("fence.proxy.async.shared::cta;" ::: "memory");
        const uint32_t s_base = smem_u32(out_s);
        #pragma unroll
        for (int ii = 0; ii < 8; ++ii) {
            float* gdst = out + ((size_t)(b * NN + i0 + ii) * NN + j0) * KK;
            asm volatile(
                "cp.async.bulk.global.shared::cta.bulk_group [%0], [%1], %2;"
                :: "l"(gdst), "r"(s_base + ii * 4096), "n"(4096) : "memory");
        }
        asm volatile("cp.async.bulk.commit_group;" ::: "memory");
        asm volatile("cp.async.bulk.wait_group 0;" ::: "memory");
    }
}

extern "C" void kernel_launch(void* const* d_in, const int* in_sizes, int n_in,
                              void* d_out, int out_size)
{
    const float* vf   = (const float*)d_in[0]; // (8,128,3,64)
    const float* dist = (const float*)d_in[1]; // (8,128,128,3)
    const float* w_vs = (const float*)d_in[2]; // (128,64)
    const float* b_vs = (const float*)d_in[3]; // (64,)
    float* out = (float*)d_out;                // (8,128,128,64)

    (void)in_sizes; (void)n_in; (void)out_size;

    proj_kernel<<<96, 256>>>(vf, w_vs, b_vs);

    // PDL launch of fuse_kernel (overlaps proj's tail; data dep via wait)
    cudaLaunchConfig_t cfg = {};
    cfg.gridDim  = dim3(8, 16, 8);
    cfg.blockDim = dim3(256, 1, 1);
    cfg.dynamicSmemBytes = 0;
    cfg.stream = 0;
    cudaLaunchAttribute attr[1];
    attr[0].id = cudaLaunchAttributeProgrammaticStreamSerialization;
    attr[0].val.programmaticStreamSerializationAllowed = 1;
    cfg.attrs = attr;
    cfg.numAttrs = 1;
    cudaError_t e = cudaLaunchKernelEx(&cfg, fuse_kernel, dist, (float*)out);
    if (e != cudaSuccess) {
        fuse_kernel<<<dim3(8, 16, 8), 256>>>(dist, out);
    }
}

// round 15
// speedup vs baseline: 1.0920x; 1.0920x over previous
#include <cuda_runtime.h>
#include <cuda_bf16.h>
#include <cstdint>

// Problem constants
#define BB 8
#define NN 128
#define CC 3
#define FF 64
#define KK 64

// Scratch for projections: p[row][kk], row = (b*N+n)*C+c (3072 rows), kk in [0,128):
// kk<64 -> p_i + b_vs (bias folded in), kk>=64 -> p_j.
__device__ float g_p[BB * NN * CC * 128];

// ---- packed f32x2 helpers (sm_100+) --------------------------------------
__device__ __forceinline__ unsigned long long pk2(float v) {
    unsigned long long r; asm("mov.b64 %0, {%1, %1};" : "=l"(r) : "f"(v)); return r;
}
__device__ __forceinline__ unsigned long long add2(unsigned long long a, unsigned long long b) {
    unsigned long long r; asm("add.rn.f32x2 %0, %1, %2;" : "=l"(r) : "l"(a), "l"(b)); return r;
}
__device__ __forceinline__ unsigned long long mul2(unsigned long long a, unsigned long long b) {
    unsigned long long r; asm("mul.rn.f32x2 %0, %1, %2;" : "=l"(r) : "l"(a), "l"(b)); return r;
}
__device__ __forceinline__ unsigned long long fma2(unsigned long long a, unsigned long long b,
                                                   unsigned long long c) {
    unsigned long long r; asm("fma.rn.f32x2 %0, %1, %2, %3;" : "=l"(r) : "l"(a), "l"(b), "l"(c));
    return r;
}
__device__ __forceinline__ void unpk2(unsigned long long p, float& lo, float& hi) {
    asm("mov.b64 {%0, %1}, %2;" : "=f"(lo), "=f"(hi) : "l"(p));
}
__device__ __forceinline__ uint32_t smem_u32(const void* p) {
    uint32_t a;
    asm("{ .reg .u64 t; cvta.to.shared.u64 t, %1; cvt.u32.u64 %0, t; }" : "=r"(a) : "l"(p));
    return a;
}
#define CP16(dst, src) \
    asm volatile("cp.async.cg.shared.global [%0], [%1], 16;" \
                 :: "r"(smem_u32(dst)), "l"(src) : "memory")

// ---------------------------------------------------------------------------
// Kernel 1: p[row][kk] = sum_f vf[row][f] * ws[f][kk]  (+ b_vs[kk] if kk<64)
// 96 blocks x 256 threads; 32 rows per block.
// ---------------------------------------------------------------------------
__global__ __launch_bounds__(256)
void proj_kernel(const float* __restrict__ vf, const float* __restrict__ w,
                 const float* __restrict__ bvs)
{
    __shared__ float ws[FF * 128];   // 32 KB: rearranged weights [f][kk]
    __shared__ float vfs[32 * FF];   // 8 KB: this block's 32 vf rows

    const int tid = threadIdx.x;

    #pragma unroll
    for (int idx = tid; idx < FF * 128; idx += 256) {
        int f  = idx >> 7;
        int kk = idx & 127;
        ws[idx] = (kk < 64) ? w[f * 64 + kk] : w[(64 + f) * 64 + (kk - 64)];
    }

    const int r0 = blockIdx.x * 32;
    const float4* vf4 = reinterpret_cast<const float4*>(vf + (size_t)r0 * FF);
    float4* vfs4 = reinterpret_cast<float4*>(vfs);
    #pragma unroll
    for (int idx = tid; idx < 32 * (FF / 4); idx += 256)
        vfs4[idx] = vf4[idx];

    __syncthreads();

    const int kg = tid & 31;   // float4 group over kk
    const int rv = tid >> 5;   // 0..7

    float4 acc0 = make_float4(0.f, 0.f, 0.f, 0.f);
    float4 acc1 = acc0, acc2 = acc0, acc3 = acc0;

    const float4* ws4 = reinterpret_cast<const float4*>(ws); // [64][32]

    #pragma unroll 8
    for (int f = 0; f < FF; ++f) {
        float4 w4 = ws4[f * 32 + kg];
        float v0 = vfs[(rv     ) * FF + f];
        float v1 = vfs[(rv +  8) * FF + f];
        float v2 = vfs[(rv + 16) * FF + f];
        float v3 = vfs[(rv + 24) * FF + f];
        acc0.x += v0 * w4.x; acc0.y += v0 * w4.y; acc0.z += v0 * w4.z; acc0.w += v0 * w4.w;
        acc1.x += v1 * w4.x; acc1.y += v1 * w4.y; acc1.z += v1 * w4.z; acc1.w += v1 * w4.w;
        acc2.x += v2 * w4.x; acc2.y += v2 * w4.y; acc2.z += v2 * w4.z; acc2.w += v2 * w4.w;
        acc3.x += v3 * w4.x; acc3.y += v3 * w4.y; acc3.z += v3 * w4.z; acc3.w += v3 * w4.w;
    }

    if (kg < 16) {   // bias folded into the p_i half
        const float4 bv = reinterpret_cast<const float4*>(bvs)[kg];
        acc0.x += bv.x; acc0.y += bv.y; acc0.z += bv.z; acc0.w += bv.w;
        acc1.x += bv.x; acc1.y += bv.y; acc1.z += bv.z; acc1.w += bv.w;
        acc2.x += bv.x; acc2.y += bv.y; acc2.z += bv.z; acc2.w += bv.w;
        acc3.x += bv.x; acc3.y += bv.y; acc3.z += bv.z; acc3.w += bv.w;
    }

    float4* p4 = reinterpret_cast<float4*>(g_p); // [3072][32]
    p4[(size_t)(r0 + rv     ) * 32 + kg] = acc0;
    p4[(size_t)(r0 + rv +  8) * 32 + kg] = acc1;
    p4[(size_t)(r0 + rv + 16) * 32 + kg] = acc2;
    p4[(size_t)(r0 + rv + 24) * 32 + kg] = acc3;
}

// ---------------------------------------------------------------------------
// Kernel 2: out[b,i,j,k] = relu( sum_c d[b,i,j,c] * (p_i'[b,i,c,k] + p_j[b,j,c,k]) )
// grid (jg=8, it=8, b=8) = 512 blocks x 256 threads.
// Each block processes TWO 8i x 16j tiles (i0 and i0+64) for one (j0, b):
//   - cp.async double-buffered staging: tile1's staging latency hides under
//     tile0's compute; tile0's hides under tile1-issue + pj loads.
//   - pj registers loaded ONCE, reused for both tiles.
// Compute body = proven R12 packed-f32x2 loop; (256,6) -> 40-reg class.
// ---------------------------------------------------------------------------
__global__ __launch_bounds__(256, 6)
void fuse_kernel(const float* __restrict__ dist,
                 float* __restrict__ out)
{
    __shared__ float4 pi_s[2][24 * 16];   // 2 x 6 KB
    __shared__ float  dist_s[2][8 * 48];  // 2 x 1.5 KB (raw layout)

    const int tid = threadIdx.x;
    const int kq  = tid & 15;   // k quad: k = kq*4
    const int jl  = tid >> 4;   // 0..15
    const int j0  = blockIdx.x * 16;
    const int it  = blockIdx.y; // 0..7
    const int b   = blockIdx.z;
    const int i0a = it * 8;
    const int i0b = 64 + it * 8;

    const float4* p4 = reinterpret_cast<const float4*>(g_p);        // [3072][32]
    const ulonglong2* p4u = reinterpret_cast<const ulonglong2*>(g_p);

    const int r  = tid >> 4, kk = tid & 15;     // staging coords (256 ops)
    const int r2 = (tid + 256) >> 4, kk2 = tid & 15; // second batch (128 ops)

    // ---- Issue tile0 staging (group 0) ----
    {
        const int rowbase = (b * NN + i0a) * CC;
        CP16(&pi_s[0][tid], &p4[(size_t)(rowbase + r) * 32 + kk]);
        if (tid < 128)
            CP16(&pi_s[0][tid + 256], &p4[(size_t)(rowbase + r2) * 32 + kk2]);
        if (tid < 96) {
            const int ii = tid / 12, q = tid % 12;
            CP16(&dist_s[0][ii * 48 + q * 4],
                 dist + (size_t)(b * NN + i0a + ii) * NN * CC + j0 * CC + q * 4);
        }
    }
    asm volatile("cp.async.commit_group;" ::: "memory");

    // ---- Issue tile1 staging (group 1) ----
    {
        const int rowbase = (b * NN + i0b) * CC;
        CP16(&pi_s[1][tid], &p4[(size_t)(rowbase + r) * 32 + kk]);
        if (tid < 128)
            CP16(&pi_s[1][tid + 256], &p4[(size_t)(rowbase + r2) * 32 + kk2]);
        if (tid < 96) {
            const int ii = tid / 12, q = tid % 12;
            CP16(&dist_s[1][ii * 48 + q * 4],
                 dist + (size_t)(b * NN + i0b + ii) * NN * CC + j0 * CC + q * 4);
        }
    }
    asm volatile("cp.async.commit_group;" ::: "memory");

    // ---- pj registers: one load, serves BOTH tiles ----
    const int j = j0 + jl;
    const int rowj = (b * NN + j) * CC;
    const ulonglong2 pj0 = p4u[(size_t)(rowj    ) * 32 + 16 + kq];
    const ulonglong2 pj1 = p4u[(size_t)(rowj + 1) * 32 + 16 + kq];
    const ulonglong2 pj2 = p4u[(size_t)(rowj + 2) * 32 + 16 + kq];

    // ---- Tile 0 ----
    asm volatile("cp.async.wait_group 1;" ::: "memory");
    __syncthreads();
    {
        const ulonglong2* pi_u = reinterpret_cast<const ulonglong2*>(pi_s[0]);
        float4* obase = reinterpret_cast<float4*>(out)
                      + ((size_t)(b * NN + i0a) * NN + j) * 16 + kq;
        #pragma unroll
        for (int ii = 0; ii < 8; ++ii) {
            const ulonglong2 pi0 = pi_u[(ii * 3 + 0) * 16 + kq];
            const ulonglong2 pi1 = pi_u[(ii * 3 + 1) * 16 + kq];
            const ulonglong2 pi2 = pi_u[(ii * 3 + 2) * 16 + kq];
            const unsigned long long d0 = pk2(dist_s[0][ii * 48 + jl * 3 + 0]);
            const unsigned long long d1 = pk2(dist_s[0][ii * 48 + jl * 3 + 1]);
            const unsigned long long d2 = pk2(dist_s[0][ii * 48 + jl * 3 + 2]);

            unsigned long long alo = mul2(d0, add2(pi0.x, pj0.x));
            alo = fma2(d1, add2(pi1.x, pj1.x), alo);
            alo = fma2(d2, add2(pi2.x, pj2.x), alo);
            unsigned long long ahi = mul2(d0, add2(pi0.y, pj0.y));
            ahi = fma2(d1, add2(pi1.y, pj1.y), ahi);
            ahi = fma2(d2, add2(pi2.y, pj2.y), ahi);

            float4 a;
            unpk2(alo, a.x, a.y);
            unpk2(ahi, a.z, a.w);
            a.x = fmaxf(a.x, 0.f); a.y = fmaxf(a.y, 0.f);
            a.z = fmaxf(a.z, 0.f); a.w = fmaxf(a.w, 0.f);
            obase[(size_t)ii * NN * 16] = a;
        }
    }

    // ---- Tile 1 ----
    asm volatile("cp.async.wait_group 0;" ::: "memory");
    __syncthreads();
    {
        const ulonglong2* pi_u = reinterpret_cast<const ulonglong2*>(pi_s[1]);
        float4* obase = reinterpret_cast<float4*>(out)
                      + ((size_t)(b * NN + i0b) * NN + j) * 16 + kq;
        #pragma unroll
        for (int ii = 0; ii < 8; ++ii) {
            const ulonglong2 pi0 = pi_u[(ii * 3 + 0) * 16 + kq];
            const ulonglong2 pi1 = pi_u[(ii * 3 + 1) * 16 + kq];
            const ulonglong2 pi2 = pi_u[(ii * 3 + 2) * 16 + kq];
            const unsigned long long d0 = pk2(dist_s[1][ii * 48 + jl * 3 + 0]);
            const unsigned long long d1 = pk2(dist_s[1][ii * 48 + jl * 3 + 1]);
            const unsigned long long d2 = pk2(dist_s[1][ii * 48 + jl * 3 + 2]);

            unsigned long long alo = mul2(d0, add2(pi0.x, pj0.x));
            alo = fma2(d1, add2(pi1.x, pj1.x), alo);
            alo = fma2(d2, add2(pi2.x, pj2.x), alo);
            unsigned long long ahi = mul2(d0, add2(pi0.y, pj0.y));
            ahi = fma2(d1, add2(pi1.y, pj1.y), ahi);
            ahi = fma2(d2, add2(pi2.y, pj2.y), ahi);

            float4 a;
            unpk2(alo, a.x, a.y);
            unpk2(ahi, a.z, a.w);
            a.x = fmaxf(a.x, 0.f); a.y = fmaxf(a.y, 0.f);
            a.z = fmaxf(a.z, 0.f); a.w = fmaxf(a.w, 0.f);
            obase[(size_t)ii * NN * 16] = a;
        }
    }
}

extern "C" void kernel_launch(void* const* d_in, const int* in_sizes, int n_in,
                              void* d_out, int out_size)
{
    const float* vf   = (const float*)d_in[0]; // (8,128,3,64)
    const float* dist = (const float*)d_in[1]; // (8,128,128,3)
    const float* w_vs = (const float*)d_in[2]; // (128,64)
    const float* b_vs = (const float*)d_in[3]; // (64,)
    float* out = (float*)d_out;                // (8,128,128,64)

    (void)in_sizes; (void)n_in; (void)out_size;

    proj_kernel<<<96, 256>>>(vf, w_vs, b_vs);
    fuse_kernel<<<dim3(8, 8, 8), 256>>>(dist, out);
}

// round 17
// speedup vs baseline: 1.1533x; 1.0562x over previous
#include <cuda_runtime.h>
#include <cuda_bf16.h>
#include <cstdint>

// Problem constants
#define BB 8
#define NN 128
#define CC 3
#define FF 64
#define KK 64

// Scratch for projections: p[row][kk], row = (b*N+n)*C+c (3072 rows), kk in [0,128):
// kk<64 -> p_i + b_vs (bias folded in), kk>=64 -> p_j.
__device__ float g_p[BB * NN * CC * 128];

// ---- packed f32x2 helpers (sm_100+) --------------------------------------
__device__ __forceinline__ unsigned long long pk2(float v) {
    unsigned long long r; asm("mov.b64 %0, {%1, %1};" : "=l"(r) : "f"(v)); return r;
}
__device__ __forceinline__ unsigned long long add2(unsigned long long a, unsigned long long b) {
    unsigned long long r; asm("add.rn.f32x2 %0, %1, %2;" : "=l"(r) : "l"(a), "l"(b)); return r;
}
__device__ __forceinline__ unsigned long long mul2(unsigned long long a, unsigned long long b) {
    unsigned long long r; asm("mul.rn.f32x2 %0, %1, %2;" : "=l"(r) : "l"(a), "l"(b)); return r;
}
__device__ __forceinline__ unsigned long long fma2(unsigned long long a, unsigned long long b,
                                                   unsigned long long c) {
    unsigned long long r; asm("fma.rn.f32x2 %0, %1, %2, %3;" : "=l"(r) : "l"(a), "l"(b), "l"(c));
    return r;
}
__device__ __forceinline__ void unpk2(unsigned long long p, float& lo, float& hi) {
    asm("mov.b64 {%0, %1}, %2;" : "=f"(lo), "=f"(hi) : "l"(p));
}
__device__ __forceinline__ uint32_t smem_u32(const void* p) {
    uint32_t a;
    asm("{ .reg .u64 t; cvta.to.shared.u64 t, %1; cvt.u32.u64 %0, t; }" : "=r"(a) : "l"(p));
    return a;
}
#define CP16(dst, src) \
    asm volatile("cp.async.cg.shared.global [%0], [%1], 16;" \
                 :: "r"(smem_u32(dst)), "l"(src) : "memory")

// ---------------------------------------------------------------------------
// Kernel 1: p[row][kk] = sum_f vf[row][f] * ws[f][kk]  (+ b_vs[kk] if kk<64)
// 96 blocks x 256 threads; 32 rows per block. Ends with PDL launch_dependents.
// ---------------------------------------------------------------------------
__global__ __launch_bounds__(256)
void proj_kernel(const float* __restrict__ vf, const float* __restrict__ w,
                 const float* __restrict__ bvs)
{
    __shared__ float ws[FF * 128];   // 32 KB: rearranged weights [f][kk]
    __shared__ float vfs[32 * FF];   // 8 KB: this block's 32 vf rows

    const int tid = threadIdx.x;

    #pragma unroll
    for (int idx = tid; idx < FF * 128; idx += 256) {
        int f  = idx >> 7;
        int kk = idx & 127;
        ws[idx] = (kk < 64) ? w[f * 64 + kk] : w[(64 + f) * 64 + (kk - 64)];
    }

    const int r0 = blockIdx.x * 32;
    const float4* vf4 = reinterpret_cast<const float4*>(vf + (size_t)r0 * FF);
    float4* vfs4 = reinterpret_cast<float4*>(vfs);
    #pragma unroll
    for (int idx = tid; idx < 32 * (FF / 4); idx += 256)
        vfs4[idx] = vf4[idx];

    __syncthreads();

    const int kg = tid & 31;   // float4 group over kk
    const int rv = tid >> 5;   // 0..7

    float4 acc0 = make_float4(0.f, 0.f, 0.f, 0.f);
    float4 acc1 = acc0, acc2 = acc0, acc3 = acc0;

    const float4* ws4 = reinterpret_cast<const float4*>(ws); // [64][32]

    #pragma unroll 8
    for (int f = 0; f < FF; ++f) {
        float4 w4 = ws4[f * 32 + kg];
        float v0 = vfs[(rv     ) * FF + f];
        float v1 = vfs[(rv +  8) * FF + f];
        float v2 = vfs[(rv + 16) * FF + f];
        float v3 = vfs[(rv + 24) * FF + f];
        acc0.x += v0 * w4.x; acc0.y += v0 * w4.y; acc0.z += v0 * w4.z; acc0.w += v0 * w4.w;
        acc1.x += v1 * w4.x; acc1.y += v1 * w4.y; acc1.z += v1 * w4.z; acc1.w += v1 * w4.w;
        acc2.x += v2 * w4.x; acc2.y += v2 * w4.y; acc2.z += v2 * w4.z; acc2.w += v2 * w4.w;
        acc3.x += v3 * w4.x; acc3.y += v3 * w4.y; acc3.z += v3 * w4.z; acc3.w += v3 * w4.w;
    }

    if (kg < 16) {   // bias folded into the p_i half
        const float4 bv = reinterpret_cast<const float4*>(bvs)[kg];
        acc0.x += bv.x; acc0.y += bv.y; acc0.z += bv.z; acc0.w += bv.w;
        acc1.x += bv.x; acc1.y += bv.y; acc1.z += bv.z; acc1.w += bv.w;
        acc2.x += bv.x; acc2.y += bv.y; acc2.z += bv.z; acc2.w += bv.w;
        acc3.x += bv.x; acc3.y += bv.y; acc3.z += bv.z; acc3.w += bv.w;
    }

    float4* p4 = reinterpret_cast<float4*>(g_p); // [3072][32]
    p4[(size_t)(r0 + rv     ) * 32 + kg] = acc0;
    p4[(size_t)(r0 + rv +  8) * 32 + kg] = acc1;
    p4[(size_t)(r0 + rv + 16) * 32 + kg] = acc2;
    p4[(size_t)(r0 + rv + 24) * 32 + kg] = acc3;

    asm volatile("griddepcontrol.launch_dependents;" ::: "memory");
}

// ---------------------------------------------------------------------------
// Kernel 2: out[b,i,j,k] = relu( sum_c d[b,i,j,c] * (p_i'[b,i,c,k] + p_j[b,j,c,k]) )
// grid (jg=8, it=8, b=8) = 512 blocks x 256 threads.
// Each block: TWO 8i x 16j tiles (i0, i0+64) for one (j0, b).
//   Group 0: dist cp.asyncs for BOTH tiles — issued BEFORE griddepcontrol.wait
//            (independent of g_p), overlapping proj's drain (PDL).
//   Groups 1/2: pi tile0 / tile1 cp.asyncs after the wait; pj LDGs once.
//   wait_group 1 -> compute tile0;  wait_group 0 -> compute tile1
//   (tile1 staging latency hidden under tile0 compute).
// Compute body = proven packed-f32x2 loop; (256,6) -> 40-reg class.
// ---------------------------------------------------------------------------
__global__ __launch_bounds__(256, 6)
void fuse_kernel(const float* __restrict__ dist,
                 float* __restrict__ out)
{
    __shared__ float4 pi_s[2][24 * 16];   // 2 x 6 KB
    __shared__ float  dist_s[2][8 * 48];  // 2 x 1.5 KB (raw layout)

    const int tid = threadIdx.x;
    const int kq  = tid & 15;   // k quad: k = kq*4
    const int jl  = tid >> 4;   // 0..15
    const int j0  = blockIdx.x * 16;
    const int it  = blockIdx.y; // 0..7
    const int b   = blockIdx.z;
    const int i0a = it * 8;
    const int i0b = 64 + it * 8;

    // ---- Group 0: dist for both tiles (independent of proj's g_p) ----
    if (tid < 96) {
        const int ii = tid / 12, q = tid % 12;
        CP16(&dist_s[0][ii * 48 + q * 4],
             dist + (size_t)(b * NN + i0a + ii) * NN * CC + j0 * CC + q * 4);
    } else if (tid < 192) {
        const int t2 = tid - 96;
        const int ii = t2 / 12, q = t2 % 12;
        CP16(&dist_s[1][ii * 48 + q * 4],
             dist + (size_t)(b * NN + i0b + ii) * NN * CC + j0 * CC + q * 4);
    }
    asm volatile("cp.async.commit_group;" ::: "memory");

    // ---- PDL wait: proj's g_p stores visible after this ----
    asm volatile("griddepcontrol.wait;" ::: "memory");

    const float4* p4 = reinterpret_cast<const float4*>(g_p);        // [3072][32]
    const ulonglong2* p4u = reinterpret_cast<const ulonglong2*>(g_p);

    const int r  = tid >> 4, kk = tid & 15;          // staging coords
    const int r2 = (tid + 256) >> 4, kk2 = tid & 15; // second batch

    // ---- Group 1: pi tile0 ----
    {
        const int rowbase = (b * NN + i0a) * CC;
        CP16(&pi_s[0][tid], &p4[(size_t)(rowbase + r) * 32 + kk]);
        if (tid < 128)
            CP16(&pi_s[0][tid + 256], &p4[(size_t)(rowbase + r2) * 32 + kk2]);
    }
    asm volatile("cp.async.commit_group;" ::: "memory");

    // ---- Group 2: pi tile1 ----
    {
        const int rowbase = (b * NN + i0b) * CC;
        CP16(&pi_s[1][tid], &p4[(size_t)(rowbase + r) * 32 + kk]);
        if (tid < 128)
            CP16(&pi_s[1][tid + 256], &p4[(size_t)(rowbase + r2) * 32 + kk2]);
    }
    asm volatile("cp.async.commit_group;" ::: "memory");

    // ---- pj registers: one load, serves BOTH tiles ----
    const int j = j0 + jl;
    const int rowj = (b * NN + j) * CC;
    const ulonglong2 pj0 = p4u[(size_t)(rowj    ) * 32 + 16 + kq];
    const ulonglong2 pj1 = p4u[(size_t)(rowj + 1) * 32 + 16 + kq];
    const ulonglong2 pj2 = p4u[(size_t)(rowj + 2) * 32 + 16 + kq];

    // ---- Tile 0 ----
    asm volatile("cp.async.wait_group 1;" ::: "memory");
    __syncthreads();
    {
        const ulonglong2* pi_u = reinterpret_cast<const ulonglong2*>(pi_s[0]);
        float4* obase = reinterpret_cast<float4*>(out)
                      + ((size_t)(b * NN + i0a) * NN + j) * 16 + kq;
        #pragma unroll
        for (int ii = 0; ii < 8; ++ii) {
            const ulonglong2 pi0 = pi_u[(ii * 3 + 0) * 16 + kq];
            const ulonglong2 pi1 = pi_u[(ii * 3 + 1) * 16 + kq];
            const ulonglong2 pi2 = pi_u[(ii * 3 + 2) * 16 + kq];
            const unsigned long long d0 = pk2(dist_s[0][ii * 48 + jl * 3 + 0]);
            const unsigned long long d1 = pk2(dist_s[0][ii * 48 + jl * 3 + 1]);
            const unsigned long long d2 = pk2(dist_s[0][ii * 48 + jl * 3 + 2]);

            unsigned long long alo = mul2(d0, add2(pi0.x, pj0.x));
            alo = fma2(d1, add2(pi1.x, pj1.x), alo);
            alo = fma2(d2, add2(pi2.x, pj2.x), alo);
            unsigned long long ahi = mul2(d0, add2(pi0.y, pj0.y));
            ahi = fma2(d1, add2(pi1.y, pj1.y), ahi);
            ahi = fma2(d2, add2(pi2.y, pj2.y), ahi);

            float4 a;
            unpk2(alo, a.x, a.y);
            unpk2(ahi, a.z, a.w);
            a.x = fmaxf(a.x, 0.f); a.y = fmaxf(a.y, 0.f);
            a.z = fmaxf(a.z, 0.f); a.w = fmaxf(a.w, 0.f);
            obase[(size_t)ii * NN * 16] = a;
        }
    }

    // ---- Tile 1 ----
    asm volatile("cp.async.wait_group 0;" ::: "memory");
    __syncthreads();
    {
        const ulonglong2* pi_u = reinterpret_cast<const ulonglong2*>(pi_s[1]);
        float4* obase = reinterpret_cast<float4*>(out)
                      + ((size_t)(b * NN + i0b) * NN + j) * 16 + kq;
        #pragma unroll
        for (int ii = 0; ii < 8; ++ii) {
            const ulonglong2 pi0 = pi_u[(ii * 3 + 0) * 16 + kq];
            const ulonglong2 pi1 = pi_u[(ii * 3 + 1) * 16 + kq];
            const ulonglong2 pi2 = pi_u[(ii * 3 + 2) * 16 + kq];
            const unsigned long long d0 = pk2(dist_s[1][ii * 48 + jl * 3 + 0]);
            const unsigned long long d1 = pk2(dist_s[1][ii * 48 + jl * 3 + 1]);
            const unsigned long long d2 = pk2(dist_s[1][ii * 48 + jl * 3 + 2]);

            unsigned long long alo = mul2(d0, add2(pi0.x, pj0.x));
            alo = fma2(d1, add2(pi1.x, pj1.x), alo);
            alo = fma2(d2, add2(pi2.x, pj2.x), alo);
            unsigned long long ahi = mul2(d0, add2(pi0.y, pj0.y));
            ahi = fma2(d1, add2(pi1.y, pj1.y), ahi);
            ahi = fma2(d2, add2(pi2.y, pj2.y), ahi);

            float4 a;
            unpk2(alo, a.x, a.y);
            unpk2(ahi, a.z, a.w);
            a.x = fmaxf(a.x, 0.f); a.y = fmaxf(a.y, 0.f);
            a.z = fmaxf(a.z, 0.f); a.w = fmaxf(a.w, 0.f);
            obase[(size_t)ii * NN * 16] = a;
        }
    }
}

extern "C" void kernel_launch(void* const* d_in, const int* in_sizes, int n_in,
                              void* d_out, int out_size)
{
    const float* vf   = (const float*)d_in[0]; // (8,128,3,64)
    const float* dist = (const float*)d_in[1]; // (8,128,128,3)
    const float* w_vs = (const float*)d_in[2]; // (128,64)
    const float* b_vs = (const float*)d_in[3]; // (64,)
    float* out = (float*)d_out;                // (8,128,128,64)

    (void)in_sizes; (void)n_in; (void)out_size;

    proj_kernel<<<96, 256>>>(vf, w_vs, b_vs);

    // PDL launch of fuse_kernel (dist staging overlaps proj's drain)
    cudaLaunchConfig_t cfg = {};
    cfg.gridDim  = dim3(8, 8, 8);
    cfg.blockDim = dim3(256, 1, 1);
    cfg.dynamicSmemBytes = 0;
    cfg.stream = 0;
    cudaLaunchAttribute attr[1];
    attr[0].id = cudaLaunchAttributeProgrammaticStreamSerialization;
    attr[0].val.programmaticStreamSerializationAllowed = 1;
    cfg.attrs = attr;
    cfg.numAttrs = 1;
    cudaError_t e = cudaLaunchKernelEx(&cfg, fuse_kernel, dist, (float*)out);
    if (e != cudaSuccess) {
        fuse_kernel<<<dim3(8, 8, 8), 256>>>(dist, out);
    }
}